// round 4
// baseline (speedup 1.0000x reference)
#include <cuda_runtime.h>
#include <math.h>

#define BB   1024
#define TT   64
#define FF   18
#define UU   128
#define G3   384
#define NCH  8            // recurrence chunk size

// 100 MB scratch for XZ = X @ kernel + bias, layout [b][t][3][128]
__device__ float g_xz[(size_t)BB * TT * 3 * UU];

// ============================================================================
// Kernel A: XZ GEMM. One CTA per batch row b; thread u owns unit u.
// (az,ar) computed with packed fma.rn.f32x2; ah scalar. Fully parallel.
// ============================================================================
__global__ __launch_bounds__(128)
void xz_gemm(const float* __restrict__ inputs,   // [B, T, F]
             const float* __restrict__ wk,       // [F, 3U]
             const float* __restrict__ bias)     // [3U]
{
    __shared__ float2 xd[TT * FF];               // x duplicated: (x, x)

    const int b = blockIdx.x, u = threadIdx.x;

    for (int i = u; i < TT * FF; i += 128) {
        const float v = inputs[(size_t)b * TT * FF + i];
        xd[i] = make_float2(v, v);
    }

    // weights: (wz,wr) packed pairs + wh scalar — all in registers
    unsigned long long wzr[FF];
    float wh[FF];
#pragma unroll
    for (int k = 0; k < FF; k++) {
        const float z = wk[k * G3 + u], r = wk[k * G3 + UU + u];
        asm("mov.b64 %0, {%1, %2};" : "=l"(wzr[k]) : "f"(z), "f"(r));
        wh[k] = wk[k * G3 + 2 * UU + u];
    }
    unsigned long long bzr;
    {
        const float z = bias[u], r = bias[UU + u];
        asm("mov.b64 %0, {%1, %2};" : "=l"(bzr) : "f"(z), "f"(r));
    }
    const float bh = bias[2 * UU + u];
    __syncthreads();

    float* out = g_xz + (size_t)b * TT * 3 * UU + u;
#pragma unroll 2
    for (int t = 0; t < TT; t++) {
        const unsigned long long* xp = (const unsigned long long*)(xd + t * FF);
        unsigned long long acc = bzr;
        float ah = bh;
#pragma unroll
        for (int k = 0; k < FF; k++) {
            const unsigned long long xb = xp[k];          // LDS.64 broadcast (x,x)
            asm("fma.rn.f32x2 %0, %1, %2, %0;" : "+l"(acc) : "l"(xb), "l"(wzr[k]));
            ah = fmaf(__uint_as_float((unsigned int)xb), wh[k], ah);
        }
        float az, ar;
        asm("mov.b64 {%0, %1}, %2;" : "=f"(az), "=f"(ar) : "l"(acc));
        out[(size_t)t * 3 * UU]          = az;
        out[(size_t)t * 3 * UU + UU]     = ar;
        out[(size_t)t * 3 * UU + 2 * UU] = ah;
    }
}

// ============================================================================
// Kernel B: recurrence + head. One CTA per batch row; thread u owns unit u.
// Chunks of NCH steps; a chunk with no nonzero-h step takes a barrier-free
// fast path with batched xz loads and fully independent epilogues.
// ============================================================================
__global__ __launch_bounds__(128)
void rnn_rec(const float* __restrict__ inputs,      // [B, T, F] (ids in col 0)
             const float* __restrict__ sync_states, // [NIDS, B, U]
             const float* __restrict__ rk,          // [U, 3U]
             const float* __restrict__ dw,          // [U, 64]
             const float* __restrict__ db,          // [64]
             const float* __restrict__ ow,          // [64, 1]
             const float* __restrict__ ob,          // [1]
             float* __restrict__ out)               // [B, 1]
{
    __shared__ int   ids_sh[TT];
    __shared__ int   slot_sh[TT];        // low16 = slot, bit16 = needs recurrence
    __shared__ int   chunk_flag[TT / NCH];
    __shared__ float h_cache[TT][UU];    // 32 KB
    __shared__ float h_sh[UU];

    const int b = blockIdx.x, u = threadIdx.x;

    if (u < TT) ids_sh[u] = (int)inputs[(size_t)b * TT * FF + u * FF];
    __syncthreads();

    if (u < TT) {
        const int myid = ids_sh[u];
        int s = 0;
        while (ids_sh[s] != myid) s++;                 // first occurrence, s <= u
        slot_sh[u] = s | ((s != u) ? (1 << 16) : 0);
    }
    __syncthreads();

    // bulk prefetch of first-occurrence initial states (high MLP)
#pragma unroll 4
    for (int t = 0; t < TT; t++) {
        if ((slot_sh[t] & 0xFFFF) == t) {
            const float v = __ldcs(&sync_states[((size_t)ids_sh[t] * BB + b) * UU + u]);
            h_cache[t][u] = v;
            if (v != 0.0f) atomicOr(&slot_sh[t], 1 << 16);
        }
    }
    __syncthreads();

    if (u < TT / NCH) {
        int f = 0;
        for (int j = 0; j < NCH; j++) f |= slot_sh[u * NCH + j];
        chunk_flag[u] = f >> 16;
    }
    __syncthreads();

    const float* xzp = g_xz + (size_t)b * TT * 3 * UU + u;
    float h_last = 0.0f;

#pragma unroll 1
    for (int tc = 0; tc < TT; tc += NCH) {
        if (!chunk_flag[tc / NCH]) {
            // fast path: every step in chunk has h == 0 (proved by flags)
            float xza[NCH], xzh[NCH];
#pragma unroll
            for (int j = 0; j < NCH; j++) {             // batched loads, MLP=16
                const float* p = xzp + (size_t)(tc + j) * 3 * UU;
                xza[j] = __ldcs(p);
                xzh[j] = __ldcs(p + 2 * UU);
            }
#pragma unroll
            for (int j = 0; j < NCH; j++) {             // independent epilogues
                const int   slot = slot_sh[tc + j] & 0xFFFF;
                const float z  = __saturatef(0.2f * xza[j] + 0.5f);
                const float e  = __expf(2.0f * xzh[j]);
                const float hh = 1.0f - __fdividef(2.0f, e + 1.0f);
                const float hn = (1.0f - z) * hh;       // z*h_u term: h_u == 0
                h_cache[slot][u] = hn;
                h_last = hn;
            }
        } else {
            // slow path: at least one step needs the recurrent GEMV
            float xzb[NCH][3];
#pragma unroll
            for (int j = 0; j < NCH; j++) {
                const float* p = xzp + (size_t)(tc + j) * 3 * UU;
                xzb[j][0] = __ldcs(p);
                xzb[j][1] = __ldcs(p + UU);
                xzb[j][2] = __ldcs(p + 2 * UU);
            }
#pragma unroll 1
            for (int j = 0; j < NCH; j++) {
                const int   sr   = slot_sh[tc + j];
                const int   slot = sr & 0xFFFF;
                const float h_u  = h_cache[slot][u];
                float gz = 0.0f, gr = 0.0f, gh = 0.0f;
                if (sr >> 16) {                          // uniform across block
                    h_sh[u] = h_u;
                    __syncthreads();
#pragma unroll 2
                    for (int k = 0; k < UU; k++) {
                        const float hv = h_sh[k];
                        const float* r = rk + k * G3;
                        gz = fmaf(hv, __ldg(r + u),          gz);
                        gr = fmaf(hv, __ldg(r + UU + u),     gr);
                        gh = fmaf(hv, __ldg(r + 2 * UU + u), gh);
                    }
                    __syncthreads();
                }
                const float z   = __saturatef(0.2f * (xzb[j][0] + gz) + 0.5f);
                const float rr  = __saturatef(0.2f * (xzb[j][1] + gr) + 0.5f);
                const float pre = xzb[j][2] + rr * gh;
                const float e   = __expf(2.0f * pre);
                const float hh  = 1.0f - __fdividef(2.0f, e + 1.0f);
                const float hn  = z * h_u + (1.0f - z) * hh;
                h_cache[slot][u] = hn;
                h_last = hn;
            }
        }
    }

    // dense head: sigmoid(relu(h @ dw + db) @ ow + ob)
    h_sh[u] = h_last;
    __syncthreads();
    float* red = (float*)slot_sh;                       // reuse smem
    if (u < 64) {
        float acc = db[u];
#pragma unroll 4
        for (int k = 0; k < UU; k++)
            acc = fmaf(h_sh[k], dw[k * 64 + u], acc);
        acc = fmaxf(acc, 0.0f) * ow[u];
#pragma unroll
        for (int o = 16; o; o >>= 1)
            acc += __shfl_down_sync(0xffffffff, acc, o);
        if ((u & 31) == 0) red[u >> 5] = acc;
    }
    __syncthreads();
    if (u == 0) {
        const float s = ob[0] + red[0] + red[1];
        out[b] = __fdividef(1.0f, 1.0f + __expf(-s));
    }
}

extern "C" void kernel_launch(void* const* d_in, const int* in_sizes, int n_in,
                              void* d_out, int out_size)
{
    const float* inputs      = (const float*)d_in[0];
    const float* sync_states = (const float*)d_in[1];
    const float* wk          = (const float*)d_in[2];
    const float* rk          = (const float*)d_in[3];
    const float* bias        = (const float*)d_in[4];
    const float* dw          = (const float*)d_in[5];
    const float* db          = (const float*)d_in[6];
    const float* ow          = (const float*)d_in[7];
    const float* ob          = (const float*)d_in[8];
    float* out = (float*)d_out;

    xz_gemm<<<BB, 128>>>(inputs, wk, bias);
    rnn_rec<<<BB, 128>>>(inputs, sync_states, rk, dw, db, ow, ob, out);
}

// round 7
// speedup vs baseline: 1.8970x; 1.8970x over previous
#include <cuda_runtime.h>
#include <math.h>

#define BB   1024
#define TT   64
#define FF   18
#define UU   128
#define G3   384
#define NR   3          // batched repeat rounds; chain pos beyond -> serial cleanup

// ---- device scratch (allocation-free) ----
__device__ float  g_xz[(size_t)BB * TT * 3 * UU];  // xz spilled for deferred steps only
__device__ float  g_h[(size_t)BB * TT * UU];       // per-(row,slot) state
__device__ float  g_hlast[(size_t)BB * UU];        // h after step T-1
__device__ float2 g_rkzr[UU * UU];                 // packed rec_kernel (z,r)
__device__ float  g_rkh[UU * UU];                  // rec_kernel h-gate
__device__ int    g_meta[BB * TT];                 // slot | (round<<8)
__device__ int    g_list[NR][BB * TT];
__device__ int    g_cnt[NR];

// ============================================================================
// prep: pack rec_kernel for vectorized GEMV; zero round counters.
// ============================================================================
__global__ void prep_k(const float* __restrict__ rk)
{
    const int i = blockIdx.x * 256 + threadIdx.x;
    if (i < UU * UU) {
        const int k = i >> 7, u = i & 127;
        g_rkzr[i] = make_float2(rk[k * G3 + u], rk[k * G3 + UU + u]);
        g_rkh[i]  = rk[k * G3 + 2 * UU + u];
    }
    if (i < NR) g_cnt[i] = 0;
}

// ============================================================================
// main: per row — slot/chain analysis, init gather + flags, xz compute fused
// with the position-0 epilogue. Deferred steps spill xz and join round lists.
// ============================================================================
__global__ __launch_bounds__(128)
void rnn_main(const float* __restrict__ inputs,      // [B, T, F]
              const float* __restrict__ sync_states, // [NIDS, B, U]
              const float* __restrict__ wk,          // [F, 3U]
              const float* __restrict__ bias)        // [3U]
{
    __shared__ float2 xd[TT * FF];       // x duplicated (x,x) for f32x2
    __shared__ int    ids_sh[TT];
    __shared__ int    slot_sh[TT];       // slot | round<<8 | repeat-later<<17

    const int b = blockIdx.x, u = threadIdx.x;

    for (int i = u; i < TT * FF; i += 128) {
        const float v = inputs[(size_t)b * TT * FF + i];
        xd[i] = make_float2(v, v);
    }

    // input-to-hidden weights in registers: (wz,wr) packed + wh scalar
    unsigned long long wzr[FF];
    float wh[FF];
#pragma unroll
    for (int k = 0; k < FF; k++) {
        const float z = wk[k * G3 + u], r = wk[k * G3 + UU + u];
        asm("mov.b64 %0, {%1, %2};" : "=l"(wzr[k]) : "f"(z), "f"(r));
        wh[k] = wk[k * G3 + 2 * UU + u];
    }
    unsigned long long bzr;
    {
        const float z = bias[u], r = bias[UU + u];
        asm("mov.b64 %0, {%1, %2};" : "=l"(bzr) : "f"(z), "f"(r));
    }
    const float bh = bias[2 * UU + u];
    __syncthreads();

    if (u < TT) ids_sh[u] = (int)xd[u * FF].x;
    __syncthreads();

    // first-occurrence slot + occurrence position
    if (u < TT) {
        const int myid = ids_sh[u];
        int s = -1, pos = 0;
        for (int j = 0; j < u; j++)
            if (ids_sh[j] == myid) { if (s < 0) s = j; pos++; }
        if (s < 0) s = u;
        slot_sh[u] = s | (pos << 8);
    }
    __syncthreads();
    if (u < TT) {
        const int sr = slot_sh[u];
        if (sr >> 8) atomicOr(&slot_sh[sr & 0xff], 1 << 17);  // slot repeats later
    }
    __syncthreads();

    // gather initial states with 8-deep MLP; flag nonzero chains (bit16)
    for (int t0 = 0; t0 < TT; t0 += 8) {
        float v[8];
#pragma unroll
        for (int j = 0; j < 8; j++)
            v[j] = __ldcs(&sync_states[((size_t)ids_sh[t0 + j] * BB + b) * UU + u]);
#pragma unroll
        for (int j = 0; j < 8; j++) {
            const int t = t0 + j, sr = slot_sh[t];
            if ((sr & 0xff) == t && v[j] != 0.0f) atomicOr(&slot_sh[t], 1 << 16);
        }
    }
    __syncthreads();

    // finalize round index r = pos + (chain init nonzero ? 1 : 0); bookkeeping
    int newv = 0;
    if (u < TT) {
        const int sr   = slot_sh[u];
        const int slot = sr & 0xff;
        const int pos  = (sr >> 8) & 0xff;
        const int r    = pos + ((slot_sh[slot] >> 16) & 1);
        newv = slot | (r << 8) | (sr & (1 << 17));
        g_meta[b * TT + u] = slot | (r << 8);
        if (r >= 1 && r <= NR) {
            const int ix = atomicAdd(&g_cnt[r - 1], 1);
            g_list[r - 1][ix] = (b << 6) | u;
        }
    }
    __syncthreads();
    if (u < TT) slot_sh[u] = newv;
    __syncthreads();

    // nonzero-init chains need h0 in the state table (rare; re-load is fine).
    // First occurrence with nonzero init <=> slot==t and round>=1.
    for (int t = 0; t < TT; t++) {
        const int sr = slot_sh[t];
        if ((sr & 0xff) == t && ((sr >> 8) & 0xff) >= 1)
            g_h[((size_t)b * TT + t) * UU + u] =
                sync_states[((size_t)ids_sh[t] * BB + b) * UU + u];
    }

    // main fused loop: xz compute + inline epilogue for round-0 steps
#pragma unroll 2
    for (int t = 0; t < TT; t++) {
        const int sr   = slot_sh[t];
        const int slot = sr & 0xff;
        const int r    = (sr >> 8) & 0xff;

        const unsigned long long* xp = (const unsigned long long*)(xd + t * FF);
        unsigned long long acc = bzr;
        float ah = bh;
#pragma unroll
        for (int k = 0; k < FF; k++) {
            const unsigned long long xb = xp[k];
            asm("fma.rn.f32x2 %0, %1, %2, %0;" : "+l"(acc) : "l"(xb), "l"(wzr[k]));
            ah = fmaf(__uint_as_float((unsigned int)xb), wh[k], ah);
        }
        float az, ar;
        asm("mov.b64 {%0, %1}, %2;" : "=f"(az), "=f"(ar) : "l"(acc));

        if (r == 0) {                         // h == 0: closed-form epilogue
            const float z  = __saturatef(0.2f * az + 0.5f);
            const float e  = __expf(2.0f * ah);
            const float hh = 1.0f - __fdividef(2.0f, e + 1.0f);
            const float hn = (1.0f - z) * hh;
            if ((sr >> 17) & 1)               // only if this id repeats later
                g_h[((size_t)b * TT + slot) * UU + u] = hn;
            if (t == TT - 1) g_hlast[(size_t)b * UU + u] = hn;
        } else {                              // deferred: spill xz triple
            float* p = g_xz + ((size_t)b * TT + t) * 3 * UU + u;
            __stcs(p, az); __stcs(p + UU, ar); __stcs(p + 2 * UU, ah);
        }
    }
}

// ============================================================================
// round_k: grid-wide batch of all chain-position-r repeat steps (independent).
// rk stays L1/L2-resident per SM across entries.
// ============================================================================
__global__ __launch_bounds__(128)
void round_k(int r)
{
    __shared__ float h_sh[UU];
    const int u = threadIdx.x;
    const int n = g_cnt[r - 1];

    for (int e = blockIdx.x; e < n; e += gridDim.x) {
        const int ent = g_list[r - 1][e];
        const int b = ent >> 6, t = ent & 63;
        const int slot = g_meta[b * TT + t] & 0xff;

        const float h_u = g_h[((size_t)b * TT + slot) * UU + u];
        h_sh[u] = h_u;
        __syncthreads();

        float gz = 0.0f, gr = 0.0f, gh = 0.0f;
#pragma unroll 4
        for (int k = 0; k < UU; k++) {
            const float  hv = h_sh[k];
            const float2 w  = __ldg(&g_rkzr[k * UU + u]);
            gz = fmaf(hv, w.x, gz);
            gr = fmaf(hv, w.y, gr);
            gh = fmaf(hv, __ldg(&g_rkh[k * UU + u]), gh);
        }

        const float* p  = g_xz + ((size_t)b * TT + t) * 3 * UU + u;
        const float az  = p[0], ar = p[UU], ah = p[2 * UU];
        const float z   = __saturatef(0.2f * (az + gz) + 0.5f);
        const float rr  = __saturatef(0.2f * (ar + gr) + 0.5f);
        const float pre = ah + rr * gh;
        const float e2  = __expf(2.0f * pre);
        const float hh  = 1.0f - __fdividef(2.0f, e2 + 1.0f);
        const float hn  = z * h_u + (1.0f - z) * hh;

        __syncthreads();                      // protect h_sh before next entry
        g_h[((size_t)b * TT + slot) * UU + u] = hn;
        if (t == TT - 1) g_hlast[(size_t)b * UU + u] = hn;
    }
}

// ============================================================================
// head_k: serial cleanup for chain positions > NR (statistically empty, kept
// for correctness), then the dense head.
// ============================================================================
__global__ __launch_bounds__(128)
void head_k(const float* __restrict__ dw, const float* __restrict__ db,
            const float* __restrict__ ow, const float* __restrict__ ob,
            float* __restrict__ out)
{
    __shared__ float h_sh[UU];
    __shared__ int   meta_sh[TT];
    __shared__ float red[2];

    const int b = blockIdx.x, u = threadIdx.x;

    if (u < TT) meta_sh[u] = g_meta[b * TT + u];
    __syncthreads();

    int any = 0;
    for (int t = 0; t < TT; t++) any |= ((meta_sh[t] >> 8) > NR);

    float hl_local = 0.0f;
    int   hl_from_local = 0;
    if (any) {                                // uniform per block
        for (int t = 0; t < TT; t++) {
            if ((meta_sh[t] >> 8) > NR) {     // uniform per block
                const int slot = meta_sh[t] & 0xff;
                const float h_u = g_h[((size_t)b * TT + slot) * UU + u];
                h_sh[u] = h_u;
                __syncthreads();
                float gz = 0.0f, gr = 0.0f, gh = 0.0f;
#pragma unroll 4
                for (int k = 0; k < UU; k++) {
                    const float  hv = h_sh[k];
                    const float2 w  = __ldg(&g_rkzr[k * UU + u]);
                    gz = fmaf(hv, w.x, gz);
                    gr = fmaf(hv, w.y, gr);
                    gh = fmaf(hv, __ldg(&g_rkh[k * UU + u]), gh);
                }
                const float* p  = g_xz + ((size_t)b * TT + t) * 3 * UU + u;
                const float z   = __saturatef(0.2f * (p[0] + gz) + 0.5f);
                const float rr  = __saturatef(0.2f * (p[UU] + gr) + 0.5f);
                const float pre = p[2 * UU] + rr * gh;
                const float e2  = __expf(2.0f * pre);
                const float hh  = 1.0f - __fdividef(2.0f, e2 + 1.0f);
                const float hn  = z * h_u + (1.0f - z) * hh;
                __syncthreads();
                g_h[((size_t)b * TT + slot) * UU + u] = hn;
                if (t == TT - 1) { hl_local = hn; hl_from_local = 1; }
            }
        }
    }

    const float hl = hl_from_local ? hl_local : g_hlast[(size_t)b * UU + u];
    __syncthreads();
    h_sh[u] = hl;
    __syncthreads();

    if (u < 64) {
        float acc = db[u];
#pragma unroll 4
        for (int k = 0; k < UU; k++)
            acc = fmaf(h_sh[k], dw[k * 64 + u], acc);
        acc = fmaxf(acc, 0.0f) * ow[u];
#pragma unroll
        for (int o = 16; o; o >>= 1)
            acc += __shfl_down_sync(0xffffffff, acc, o);
        if ((u & 31) == 0) red[u >> 5] = acc;
    }
    __syncthreads();
    if (u == 0) {
        const float s = ob[0] + red[0] + red[1];
        out[b] = __fdividef(1.0f, 1.0f + __expf(-s));
    }
}

extern "C" void kernel_launch(void* const* d_in, const int* in_sizes, int n_in,
                              void* d_out, int out_size)
{
    const float* inputs      = (const float*)d_in[0];
    const float* sync_states = (const float*)d_in[1];
    const float* wk          = (const float*)d_in[2];
    const float* rk          = (const float*)d_in[3];
    const float* bias        = (const float*)d_in[4];
    const float* dw          = (const float*)d_in[5];
    const float* db          = (const float*)d_in[6];
    const float* ow          = (const float*)d_in[7];
    const float* ob          = (const float*)d_in[8];
    float* out = (float*)d_out;

    prep_k<<<(UU * UU + 255) / 256, 256>>>(rk);
    rnn_main<<<BB, 128>>>(inputs, sync_states, wk, bias);
    round_k<<<1024, 128>>>(1);
    round_k<<<256, 128>>>(2);
    round_k<<<256, 128>>>(3);
    head_k<<<BB, 128>>>(dw, db, ow, ob, out);
}